// round 8
// baseline (speedup 1.0000x reference)
#include <cuda_runtime.h>
#include <cuda_bf16.h>

#define HH 64
#define GRID_BLOCKS 2048
#define THREADS 128

// W2^T tf32 hi/lo A-fragment tables, built once by init kernel.
// [kq][chunk][lane]: a0=W2[j0][kb+gid], a1=W2[j0][kb+gid+8], a2=W2[j1][kb+gid], a3=W2[j1][kb+gid+8]
// gid=lane>>2, tig=lane&3, j0=chunk*8+tig, j1=j0+4, kb=kq*16
__device__ uint4 gAhi[4][8][32];
__device__ uint4 gAlo[4][8][32];

// fast tanh + first three derivatives via ex2.approx + rcp.approx
__device__ __forceinline__ void tanh_derivs(float x, float& f, float& f1, float& f2, float& f3) {
    float e, r;
    asm("ex2.approx.f32 %0, %1;" : "=f"(e) : "f"(x * 2.885390081777927f)); // 2*log2(e)
    asm("rcp.approx.f32 %0, %1;" : "=f"(r) : "f"(e + 1.0f));
    f  = fmaf(-2.0f, r, 1.0f);
    f1 = 1.0f - f * f;
    f2 = -2.0f * f * f1;
    f3 = -2.0f * (f1 * f1 + f * f2);
}

// split f32 into tf32-exact hi (top 10 mantissa bits) + residual lo
__device__ __forceinline__ void tf32_split(float v, unsigned& hi, unsigned& lo) {
    unsigned h = __float_as_uint(v) & 0xFFFFE000u;
    hi = h;
    lo = __float_as_uint(v - __uint_as_float(h));
}

// mma.m16n8k8 tf32: C[4] += A(uint4) * B(b0,b1)
#define MMA_TF32(C, A, b0, b1) \
    asm("mma.sync.aligned.m16n8k8.row.col.f32.tf32.tf32.f32 " \
        "{%0,%1,%2,%3},{%4,%5,%6,%7},{%8,%9},{%0,%1,%2,%3};" \
        : "+f"((C)[0]), "+f"((C)[1]), "+f"((C)[2]), "+f"((C)[3]) \
        : "r"((A).x), "r"((A).y), "r"((A).z), "r"((A).w), "r"(b0), "r"(b1))

// split both B values for coeff c and issue the 3-term split-tf32 MMA group
#define EMIT(c, v0, v1) do { \
    unsigned _h0, _l0, _h1, _l1; \
    tf32_split((v0), _h0, _l0); \
    tf32_split((v1), _h1, _l1); \
    MMA_TF32(C[c], Ah, _h0, _h1); \
    MMA_TF32(C[c], Ah, _l0, _l1); \
    MMA_TF32(C[c], Al, _h0, _h1); \
} while (0)

// Faa di Bruno: accumulate w3 * jet(tanh(z)) into acc9[0..8] (coeffs p,t,pp,pt,tt,ppp,ppt,ptt,ttt)
__device__ __forceinline__ void compose_scalar(const float* z, float w3, float* acc9) {
    float f, f1, f2, f3;
    tanh_derivs(z[0], f, f1, f2, f3);
    const float zp = z[1], zt = z[2], zpp = z[3], zpt = z[4], ztt = z[5];
    const float zppp = z[6], zppt = z[7], zptt = z[8], zttt = z[9];
    acc9[0] = fmaf(w3, f1 * zp, acc9[0]);
    acc9[1] = fmaf(w3, f1 * zt, acc9[1]);
    acc9[2] = fmaf(w3, fmaf(f2, zp * zp, f1 * zpp), acc9[2]);
    acc9[3] = fmaf(w3, fmaf(f2, zp * zt, f1 * zpt), acc9[3]);
    acc9[4] = fmaf(w3, fmaf(f2, zt * zt, f1 * ztt), acc9[4]);
    acc9[5] = fmaf(w3, f3 * zp * zp * zp + 3.0f * f2 * zp * zpp + f1 * zppp, acc9[5]);
    acc9[6] = fmaf(w3, f3 * zp * zp * zt + f2 * (zpp * zt + 2.0f * zp * zpt) + f1 * zppt, acc9[6]);
    acc9[7] = fmaf(w3, f3 * zp * zt * zt + f2 * (ztt * zp + 2.0f * zt * zpt) + f1 * zptt, acc9[7]);
    acc9[8] = fmaf(w3, f3 * zt * zt * zt + 3.0f * f2 * zt * ztt + f1 * zttt, acc9[8]);
}

__global__ void init_A_kernel(const float* __restrict__ W2) {
    const int idx = blockIdx.x * blockDim.x + threadIdx.x;
    if (idx >= 1024) return;
    const int kq = idx >> 8, chunk = (idx >> 5) & 7, ln = idx & 31;
    const int gid = ln >> 2, tig = ln & 3;
    const int j0 = chunk * 8 + tig, j1 = j0 + 4, kb = kq * 16;
    const float a0 = W2[j0 * HH + kb + gid];
    const float a1 = W2[j0 * HH + kb + gid + 8];
    const float a2 = W2[j1 * HH + kb + gid];
    const float a3 = W2[j1 * HH + kb + gid + 8];
    unsigned h0, l0, h1, l1, h2, l2, h3, l3;
    tf32_split(a0, h0, l0);
    tf32_split(a1, h1, l1);
    tf32_split(a2, h2, l2);
    tf32_split(a3, h3, l3);
    gAhi[kq][chunk][ln] = make_uint4(h0, h1, h2, h3);
    gAlo[kq][chunk][ln] = make_uint4(l0, l1, l2, l3);
}

__global__ __launch_bounds__(THREADS, 5) void pinn_flow_kernel(
    const float* __restrict__ phi, const float* __restrict__ theta,
    const float* __restrict__ radius, const float* __restrict__ hth,
    const float* __restrict__ hph, const float* __restrict__ brr,
    const float* __restrict__ W1, const float* __restrict__ b1,
    const float* __restrict__ W2, const float* __restrict__ b2,
    const float* __restrict__ W3, const float* __restrict__ b3,
    float* __restrict__ out, int n)
{
    // jet table for the current 8-point tile: row j (stride 104 words), within row: pt*12 + c
    __shared__ __align__(16) float sB[HH][104];      // 26.6 KB
    __shared__ __align__(16) float sL1[HH][12];      // a,b,aa,ab,bb,aaa,aab,abb,bbb,b1
    __shared__ float sB2[HH];
    __shared__ float sW3[HH];
    __shared__ float sP[8], sTh[8];
    __shared__ float sTred[4][8][10];

    const int tid = threadIdx.x;
    if (tid < HH) {
        sB2[tid] = b2[tid];
        sW3[tid] = W3[tid];
        const float a = W1[tid];        // W1[0][j]
        const float b = W1[HH + tid];   // W1[1][j]
        sL1[tid][0] = a;       sL1[tid][1] = b;
        sL1[tid][2] = a * a;   sL1[tid][3] = a * b;     sL1[tid][4] = b * b;
        sL1[tid][5] = a * a * a; sL1[tid][6] = a * a * b;
        sL1[tid][7] = a * b * b; sL1[tid][8] = b * b * b;
        sL1[tid][9] = b1[tid];
        sL1[tid][10] = 0.0f; sL1[tid][11] = 0.0f;
    }
    __syncthreads();

    const int lane = tid & 31;
    const int w    = tid >> 5;         // warp = its k-quarter
    const int gid  = lane >> 2;        // 0..7 (point for B / k-row for C)
    const int tig  = lane & 3;         // 0..3
    const int ntiles = (n + 7) >> 3;   // 8 points per block-tile

    for (int tile = blockIdx.x; tile < ntiles; tile += GRID_BLOCKS) {
        const int base = tile * 8;

        if (tid < 8) {
            const int i = base + tid;
            const int iL = (i < n) ? i : (n - 1);
            sP[tid]  = phi[iL];
            sTh[tid] = theta[iL];
        }
        __syncthreads();

        // ---- Phase A (cooperative): jets for all (j, pt), once per tile ----
        #pragma unroll
        for (int q = 0; q < 4; ++q) {
            const int idx = tid + THREADS * q;      // 512 pairs
            const int j  = idx >> 3;
            const int pt = idx & 7;
            const float p = sP[pt];
            const float t = sTh[pt];
            const float4 m0 = *(const float4*)&sL1[j][0];   // a,b,aa,ab
            const float4 m1 = *(const float4*)&sL1[j][4];   // bb,aaa,aab,abb
            const float2 m2 = *(const float2*)&sL1[j][8];   // bbb,b1
            const float z1 = fmaf(m0.x, p, fmaf(m0.y, t, m2.y));
            float f, f1, f2, f3;
            tanh_derivs(z1, f, f1, f2, f3);
            float* dst = &sB[j][pt * 12];
            *(float4*)&dst[0] = make_float4(f, f1 * m0.x, f1 * m0.y, f2 * m0.z);
            *(float4*)&dst[4] = make_float4(f2 * m0.w, f2 * m1.x, f3 * m1.y, f3 * m1.z);
            *(float2*)&dst[8] = make_float2(f3 * m1.w, f3 * m2.x);
        }
        __syncthreads();

        // ---- Phase B: each warp does its k-quarter's MMAs ----
        float C[10][4];
        #pragma unroll
        for (int c = 0; c < 10; ++c) {
            C[c][0] = 0.0f; C[c][1] = 0.0f; C[c][2] = 0.0f; C[c][3] = 0.0f;
        }

        #pragma unroll 1
        for (int chunk = 0; chunk < 8; ++chunk) {
            const uint4 Ah = gAhi[w][chunk][lane];
            const uint4 Al = gAlo[w][chunk][lane];
            const float* b0p = &sB[chunk * 8 + tig][gid * 12];
            const float* b1p = &sB[chunk * 8 + tig + 4][gid * 12];
            const float4 x0 = *(const float4*)&b0p[0];
            const float4 x1 = *(const float4*)&b0p[4];
            const float2 x2 = *(const float2*)&b0p[8];
            const float4 y0 = *(const float4*)&b1p[0];
            const float4 y1 = *(const float4*)&b1p[4];
            const float2 y2 = *(const float2*)&b1p[8];
            EMIT(0, x0.x, y0.x);
            EMIT(1, x0.y, y0.y);
            EMIT(2, x0.z, y0.z);
            EMIT(3, x0.w, y0.w);
            EMIT(4, x1.x, y1.x);
            EMIT(5, x1.y, y1.y);
            EMIT(6, x1.z, y1.z);
            EMIT(7, x1.w, y1.w);
            EMIT(8, x2.x, y2.x);
            EMIT(9, x2.y, y2.y);
        }

        // ---- Phase C: compose this warp's k's, reduce over gid-lanes ----
        float Tj[18];
        #pragma unroll
        for (int q = 0; q < 18; ++q) Tj[q] = 0.0f;
        #pragma unroll
        for (int e = 0; e < 4; ++e) {
            const int k = w * 16 + gid + ((e & 2) ? 8 : 0);
            float z[10];
            #pragma unroll
            for (int c = 0; c < 10; ++c) z[c] = C[c][e];
            z[0] += sB2[k];
            compose_scalar(z, sW3[k], &Tj[(e & 1) * 9]);
        }
        #pragma unroll
        for (int q = 0; q < 18; ++q) {
            float v = Tj[q];
            v += __shfl_xor_sync(0xffffffffu, v, 4);
            v += __shfl_xor_sync(0xffffffffu, v, 8);
            v += __shfl_xor_sync(0xffffffffu, v, 16);
            Tj[q] = v;
        }
        if (lane < 4) {
            #pragma unroll
            for (int sel = 0; sel < 2; ++sel)
                #pragma unroll
                for (int cc = 0; cc < 9; ++cc)
                    sTred[w][2 * lane + sel][cc] = Tj[sel * 9 + cc];
        }
        __syncthreads();

        // ---- Epilogue: threads 0..7 finish one point each ----
        if (tid < 8) {
            const int i = base + tid;
            if (i < n) {
                float T[9];
                #pragma unroll
                for (int cc = 0; cc < 9; ++cc)
                    T[cc] = sTred[0][tid][cc] + sTred[1][tid][cc]
                          + sTred[2][tid][cc] + sTred[3][tid][cc];
                const float Tp = T[0], Tt = T[1];
                const float Tpp = T[2], Tpt = T[3], Ttt = T[4];
                const float Tppp = T[5], Tppt = T[6], Tptt = T[7], Tttt = T[8];

                const float th = sTh[tid];
                float s, cn;
                sincosf(th, &s, &cn);
                const float r    = radius[i];
                const float invs = 1.0f / s;
                const float invr = 1.0f / r;

                const float ut = fmaf(Tp, invs, Tt);
                const float up = fmaf(Tp, invs, -Tt);

                const float u_th_t = -(Tpt + cn * Tt + s * Ttt);
                const float u_ph_p = fmaf(Tpp, invs, -Tpt);
                const float div = (u_th_t + u_ph_p) * invs * invr;

                const float c2s2 = cn * cn - s * s;
                const float u_th_tt = -(cn * Tpt + s * Tptt + 3.0f * s * cn * Ttt
                                        + c2s2 * Tt + s * s * Tttt);
                const float u_th_pp = -(fmaf(Tppp, invs, Tppt));
                const float u_ph_tt = cn * Tpt + s * Tptt - c2s2 * Tt
                                      - 3.0f * s * cn * Ttt - s * s * Tttt;
                const float u_ph_pp = fmaf(Tppp, invs, -Tppt);

                const float invr2  = invr * invr;
                const float invrs2 = invs * invs * invr2;
                const float lapt = fmaf(s * invr2, u_th_tt, u_th_pp * invrs2);
                const float lapp = fmaf(s * invr2, u_ph_tt, u_ph_pp * invrs2);
                const float comp = s * (lapt * lapt + lapp * lapp);
                const float sv   = -(ut * hth[i] + up * hph[i]) - brr[i] * div;
                const float tg   = div - ut * (s / cn) * invr;

                out[i]         = ut;
                out[n + i]     = up;
                out[2 * n + i] = div;
                out[3 * n + i] = sv;
                out[4 * n + i] = tg;
                out[5 * n + i] = comp;
            }
        }
        __syncthreads();   // protect sB/sTred/sP before next tile overwrites
    }
}

extern "C" void kernel_launch(void* const* d_in, const int* in_sizes, int n_in,
                              void* d_out, int out_size) {
    const float* phi    = (const float*)d_in[0];
    const float* theta  = (const float*)d_in[1];
    const float* radius = (const float*)d_in[2];
    const float* hth    = (const float*)d_in[3];
    const float* hph    = (const float*)d_in[4];
    const float* brr    = (const float*)d_in[5];
    const float* W1     = (const float*)d_in[6];
    const float* b1     = (const float*)d_in[7];
    const float* W2     = (const float*)d_in[8];
    const float* b2     = (const float*)d_in[9];
    const float* W3     = (const float*)d_in[10];
    const float* b3     = (const float*)d_in[11];
    float* out = (float*)d_out;
    const int n = in_sizes[0];

    init_A_kernel<<<4, 256>>>(W2);
    pinn_flow_kernel<<<GRID_BLOCKS, THREADS>>>(
        phi, theta, radius, hth, hph, brr,
        W1, b1, W2, b2, W3, b3, out, n);
}

// round 9
// speedup vs baseline: 1.0575x; 1.0575x over previous
#include <cuda_runtime.h>
#include <cuda_bf16.h>

#define HH 64
#define GRID_BLOCKS 2048
#define THREADS 128

// fast tanh + first three derivatives via ex2.approx + rcp.approx
__device__ __forceinline__ void tanh_derivs(float x, float& f, float& f1, float& f2, float& f3) {
    float e, r;
    asm("ex2.approx.f32 %0, %1;" : "=f"(e) : "f"(x * 2.885390081777927f)); // 2*log2(e)
    asm("rcp.approx.f32 %0, %1;" : "=f"(r) : "f"(e + 1.0f));
    f  = fmaf(-2.0f, r, 1.0f);
    f1 = 1.0f - f * f;
    f2 = -2.0f * f * f1;
    f3 = -2.0f * (f1 * f1 + f * f2);
}

// split f32 into tf32-exact hi (top 10 mantissa bits) + residual lo
__device__ __forceinline__ void tf32_split(float v, unsigned& hi, unsigned& lo) {
    unsigned h = __float_as_uint(v) & 0xFFFFE000u;
    hi = h;
    lo = __float_as_uint(v - __uint_as_float(h));
}

// mma.m16n8k8 tf32: C[4] += A(uint4) * B(b0,b1)
#define MMA_TF32(C, A, b0, b1) \
    asm("mma.sync.aligned.m16n8k8.row.col.f32.tf32.tf32.f32 " \
        "{%0,%1,%2,%3},{%4,%5,%6,%7},{%8,%9},{%0,%1,%2,%3};" \
        : "+f"((C)[0]), "+f"((C)[1]), "+f"((C)[2]), "+f"((C)[3]) \
        : "r"((A).x), "r"((A).y), "r"((A).z), "r"((A).w), "r"(b0), "r"(b1))

// split both B values for coeff c at the point of use, then the 3-term split-tf32 group
#define EMIT(c, v0, v1) do { \
    unsigned _h0, _l0, _h1, _l1; \
    tf32_split((v0), _h0, _l0); \
    tf32_split((v1), _h1, _l1); \
    MMA_TF32(C[c], Ah, _h0, _h1); \
    MMA_TF32(C[c], Ah, _l0, _l1); \
    MMA_TF32(C[c], Al, _h0, _h1); \
} while (0)

// Faa di Bruno: accumulate w3 * jet(tanh(z)) into acc9[0..8] (coeffs p,t,pp,pt,tt,ppp,ppt,ptt,ttt)
__device__ __forceinline__ void compose_scalar(const float* z, float w3, float* acc9) {
    float f, f1, f2, f3;
    tanh_derivs(z[0], f, f1, f2, f3);
    const float zp = z[1], zt = z[2], zpp = z[3], zpt = z[4], ztt = z[5];
    const float zppp = z[6], zppt = z[7], zptt = z[8], zttt = z[9];
    acc9[0] = fmaf(w3, f1 * zp, acc9[0]);
    acc9[1] = fmaf(w3, f1 * zt, acc9[1]);
    acc9[2] = fmaf(w3, fmaf(f2, zp * zp, f1 * zpp), acc9[2]);
    acc9[3] = fmaf(w3, fmaf(f2, zp * zt, f1 * zpt), acc9[3]);
    acc9[4] = fmaf(w3, fmaf(f2, zt * zt, f1 * ztt), acc9[4]);
    acc9[5] = fmaf(w3, f3 * zp * zp * zp + 3.0f * f2 * zp * zpp + f1 * zppp, acc9[5]);
    acc9[6] = fmaf(w3, f3 * zp * zp * zt + f2 * (zpp * zt + 2.0f * zp * zpt) + f1 * zppt, acc9[6]);
    acc9[7] = fmaf(w3, f3 * zp * zt * zt + f2 * (ztt * zp + 2.0f * zt * zpt) + f1 * zptt, acc9[7]);
    acc9[8] = fmaf(w3, f3 * zt * zt * zt + 3.0f * f2 * zt * ztt + f1 * zttt, acc9[8]);
}

__global__ __launch_bounds__(THREADS, 5) void pinn_flow_kernel(
    const float* __restrict__ phi, const float* __restrict__ theta,
    const float* __restrict__ radius, const float* __restrict__ hth,
    const float* __restrict__ hph, const float* __restrict__ brr,
    const float* __restrict__ W1, const float* __restrict__ b1,
    const float* __restrict__ W2, const float* __restrict__ b2,
    const float* __restrict__ W3, const float* __restrict__ b3,
    float* __restrict__ out, int n)
{
    // A-operand tables: W2^T arranged per-lane for m16n8k8 A-fragments (hi/lo split).
    // [kq][chunk][lane]: a0=W2[j0][kb+gid], a1=W2[j0][kb+gid+8],
    //                    a2=W2[j1][kb+gid], a3=W2[j1][kb+gid+8]
    // gid=lane>>2, tig=lane&3, j0=chunk*8+tig, j1=j0+4, kb=kq*16.
    __shared__ __align__(16) uint4 sAhi[4][8][32];   // 16 KB
    __shared__ __align__(16) uint4 sAlo[4][8][32];   // 16 KB
    __shared__ __align__(16) float sL1[HH][12];      // a,b,aa,ab,bb,aaa,aab,abb,bbb,b1
    __shared__ float sB2[HH];
    __shared__ float sW3[HH];

    const int tid = threadIdx.x;

    for (int idx = tid; idx < 4 * 8 * 32; idx += THREADS) {
        const int kq    = idx >> 8;
        const int chunk = (idx >> 5) & 7;
        const int ln    = idx & 31;
        const int g = ln >> 2, tg = ln & 3;
        const int j0 = chunk * 8 + tg;
        const int j1 = j0 + 4;
        const int kb = kq * 16;
        unsigned h0, l0, h1, l1, h2, l2, h3, l3;
        tf32_split(W2[j0 * HH + kb + g],     h0, l0);
        tf32_split(W2[j0 * HH + kb + g + 8], h1, l1);
        tf32_split(W2[j1 * HH + kb + g],     h2, l2);
        tf32_split(W2[j1 * HH + kb + g + 8], h3, l3);
        sAhi[kq][chunk][ln] = make_uint4(h0, h1, h2, h3);
        sAlo[kq][chunk][ln] = make_uint4(l0, l1, l2, l3);
    }
    if (tid < HH) {
        sB2[tid] = b2[tid];
        sW3[tid] = W3[tid];
        const float a = W1[tid];        // W1[0][j]
        const float b = W1[HH + tid];   // W1[1][j]
        sL1[tid][0] = a;       sL1[tid][1] = b;
        sL1[tid][2] = a * a;   sL1[tid][3] = a * b;     sL1[tid][4] = b * b;
        sL1[tid][5] = a * a * a; sL1[tid][6] = a * a * b;
        sL1[tid][7] = a * b * b; sL1[tid][8] = b * b * b;
        sL1[tid][9] = b1[tid];
        sL1[tid][10] = 0.0f; sL1[tid][11] = 0.0f;
    }
    __syncthreads();

    const int lane = tid & 31;
    const int w    = tid >> 5;
    const int gid  = lane >> 2;   // 0..7
    const int tig  = lane & 3;    // 0..3
    const int ntiles = (n + 31) >> 5;   // 32 points per block-tile (8 per warp)

    for (int tile = blockIdx.x; tile < ntiles; tile += gridDim.x) {
        const int base = tile * 32 + w * 8;     // this warp's 8 points
        const int myp  = base + gid;            // point for B-fragment building
        const int mypL = (myp < n) ? myp : (n - 1);
        const float p = phi[mypL];
        const float t = theta[mypL];

        // T-jet partials: [col 0: coeffs 1..9][col 1: coeffs 1..9]
        float Tj[18];
        #pragma unroll
        for (int q = 0; q < 18; ++q) Tj[q] = 0.0f;

        #pragma unroll 1
        for (int kq = 0; kq < 4; ++kq) {
            float C[10][4];
            #pragma unroll
            for (int c = 0; c < 10; ++c) {
                C[c][0] = 0.0f; C[c][1] = 0.0f; C[c][2] = 0.0f; C[c][3] = 0.0f;
            }

            #pragma unroll 1
            for (int chunk = 0; chunk < 8; ++chunk) {
                // tanh-jet products for this lane's two j's, kept as plain floats
                float p0[10], p1[10];
                {
                    const int j0 = chunk * 8 + tig;
                    const float4 m0 = *(const float4*)&sL1[j0][0];   // a,b,aa,ab
                    const float4 m1 = *(const float4*)&sL1[j0][4];   // bb,aaa,aab,abb
                    const float2 m2 = *(const float2*)&sL1[j0][8];   // bbb,b1
                    const float z1 = fmaf(m0.x, p, fmaf(m0.y, t, m2.y));
                    float f, f1, f2, f3;
                    tanh_derivs(z1, f, f1, f2, f3);
                    p0[0] = f;
                    p0[1] = f1 * m0.x;  p0[2] = f1 * m0.y;
                    p0[3] = f2 * m0.z;  p0[4] = f2 * m0.w;  p0[5] = f2 * m1.x;
                    p0[6] = f3 * m1.y;  p0[7] = f3 * m1.z;  p0[8] = f3 * m1.w;
                    p0[9] = f3 * m2.x;
                }
                {
                    const int j1 = chunk * 8 + tig + 4;
                    const float4 m0 = *(const float4*)&sL1[j1][0];
                    const float4 m1 = *(const float4*)&sL1[j1][4];
                    const float2 m2 = *(const float2*)&sL1[j1][8];
                    const float z1 = fmaf(m0.x, p, fmaf(m0.y, t, m2.y));
                    float f, f1, f2, f3;
                    tanh_derivs(z1, f, f1, f2, f3);
                    p1[0] = f;
                    p1[1] = f1 * m0.x;  p1[2] = f1 * m0.y;
                    p1[3] = f2 * m0.z;  p1[4] = f2 * m0.w;  p1[5] = f2 * m1.x;
                    p1[6] = f3 * m1.y;  p1[7] = f3 * m1.z;  p1[8] = f3 * m1.w;
                    p1[9] = f3 * m2.x;
                }

                const uint4 Ah = sAhi[kq][chunk][lane];
                const uint4 Al = sAlo[kq][chunk][lane];
                #pragma unroll
                for (int c = 0; c < 10; ++c)
                    EMIT(c, p0[c], p1[c]);
            }

            // ---- compose this k-quarter's fragments into T-jet partials ----
            #pragma unroll
            for (int e = 0; e < 4; ++e) {
                const int k = kq * 16 + gid + ((e & 2) ? 8 : 0);
                float z[10];
                #pragma unroll
                for (int c = 0; c < 10; ++c) z[c] = C[c][e];
                z[0] += sB2[k];
                compose_scalar(z, sW3[k], &Tj[(e & 1) * 9]);
            }
        }

        // ---- reduce T-jet over the 8 lanes sharing each point-column ----
        #pragma unroll
        for (int q = 0; q < 18; ++q) {
            float v = Tj[q];
            v += __shfl_xor_sync(0xffffffffu, v, 4);
            v += __shfl_xor_sync(0xffffffffu, v, 8);
            v += __shfl_xor_sync(0xffffffffu, v, 16);
            Tj[q] = v;
        }

        // ---- epilogue: lanes 0..7 each finish one point ----
        if (lane < 8) {
            const int m   = lane & 3;
            const int sel = lane >> 2;
            const int pc  = 2 * m + sel;      // column within warp tile
            const int i   = base + pc;
            if (i < n) {
                const float* T = &Tj[sel * 9];
                const float Tp = T[0], Tt = T[1];
                const float Tpp = T[2], Tpt = T[3], Ttt = T[4];
                const float Tppp = T[5], Tppt = T[6], Tptt = T[7], Tttt = T[8];

                const float th = theta[i];
                float s, cn;
                sincosf(th, &s, &cn);
                const float r    = radius[i];
                const float invs = 1.0f / s;
                const float invr = 1.0f / r;

                const float ut = fmaf(Tp, invs, Tt);
                const float up = fmaf(Tp, invs, -Tt);

                const float u_th_t = -(Tpt + cn * Tt + s * Ttt);
                const float u_ph_p = fmaf(Tpp, invs, -Tpt);
                const float div = (u_th_t + u_ph_p) * invs * invr;

                const float c2s2 = cn * cn - s * s;
                const float u_th_tt = -(cn * Tpt + s * Tptt + 3.0f * s * cn * Ttt
                                        + c2s2 * Tt + s * s * Tttt);
                const float u_th_pp = -(fmaf(Tppp, invs, Tppt));
                const float u_ph_tt = cn * Tpt + s * Tptt - c2s2 * Tt
                                      - 3.0f * s * cn * Ttt - s * s * Tttt;
                const float u_ph_pp = fmaf(Tppp, invs, -Tppt);

                const float invr2  = invr * invr;
                const float invrs2 = invs * invs * invr2;
                const float lapt = fmaf(s * invr2, u_th_tt, u_th_pp * invrs2);
                const float lapp = fmaf(s * invr2, u_ph_tt, u_ph_pp * invrs2);
                const float comp = s * (lapt * lapt + lapp * lapp);
                const float sv   = -(ut * hth[i] + up * hph[i]) - brr[i] * div;
                const float tg   = div - ut * (s / cn) * invr;

                out[i]         = ut;
                out[n + i]     = up;
                out[2 * n + i] = div;
                out[3 * n + i] = sv;
                out[4 * n + i] = tg;
                out[5 * n + i] = comp;
            }
        }
    }
}

extern "C" void kernel_launch(void* const* d_in, const int* in_sizes, int n_in,
                              void* d_out, int out_size) {
    const float* phi    = (const float*)d_in[0];
    const float* theta  = (const float*)d_in[1];
    const float* radius = (const float*)d_in[2];
    const float* hth    = (const float*)d_in[3];
    const float* hph    = (const float*)d_in[4];
    const float* brr    = (const float*)d_in[5];
    const float* W1     = (const float*)d_in[6];
    const float* b1     = (const float*)d_in[7];
    const float* W2     = (const float*)d_in[8];
    const float* b2     = (const float*)d_in[9];
    const float* W3     = (const float*)d_in[10];
    const float* b3     = (const float*)d_in[11];
    float* out = (float*)d_out;
    const int n = in_sizes[0];

    pinn_flow_kernel<<<GRID_BLOCKS, THREADS>>>(
        phi, theta, radius, hth, hph, brr,
        W1, b1, W2, b2, W3, b3, out, n);
}

// round 10
// speedup vs baseline: 1.3450x; 1.2719x over previous
#include <cuda_runtime.h>
#include <cuda_bf16.h>
#include <cuda_fp16.h>

#define HH 64
#define GRID_BLOCKS 2048
#define THREADS 128

// fast tanh + first three derivatives via ex2.approx + rcp.approx
__device__ __forceinline__ void tanh_derivs(float x, float& f, float& f1, float& f2, float& f3) {
    float e, r;
    asm("ex2.approx.f32 %0, %1;" : "=f"(e) : "f"(x * 2.885390081777927f)); // 2*log2(e)
    asm("rcp.approx.f32 %0, %1;" : "=f"(r) : "f"(e + 1.0f));
    f  = fmaf(-2.0f, r, 1.0f);
    f1 = 1.0f - f * f;
    f2 = -2.0f * f * f1;
    f3 = -2.0f * (f1 * f1 + f * f2);
}

// pack two f32 into half2: first asm operand -> UPPER half
#define PACK_H2(d, hif, lof) \
    asm("cvt.rn.f16x2.f32 %0, %1, %2;" : "=r"(d) : "f"(hif), "f"(lof))

// unpack half2 -> two f32 (lo, hi)
#define UNPACK_H2(lof, hif, s) \
    asm("{.reg .f16 l, h; mov.b32 {l, h}, %2; cvt.f32.f16 %0, l; cvt.f32.f16 %1, h;}" \
        : "=f"(lof), "=f"(hif) : "r"(s))

// f32 -> value exactly representable in f16 (round trip)
__device__ __forceinline__ float h2f_round(float v) {
    float o;
    asm("{.reg .f16 t; cvt.rn.f16.f32 t, %1; cvt.f32.f16 %0, t;}" : "=f"(o) : "f"(v));
    return o;
}

// mma.m16n8k16 f16 inputs, f32 accumulate
#define MMA16(C, A, b0, b1) \
    asm("mma.sync.aligned.m16n8k16.row.col.f32.f16.f16.f32 " \
        "{%0,%1,%2,%3},{%4,%5,%6,%7},{%8,%9},{%0,%1,%2,%3};" \
        : "+f"((C)[0]), "+f"((C)[1]), "+f"((C)[2]), "+f"((C)[3]) \
        : "r"((A).x), "r"((A).y), "r"((A).z), "r"((A).w), "r"(b0), "r"(b1))

// given va..vd (B rows 2t,2t+1,2t+8,2t+9 for this lane's point-col), do 3-term split MMA
#define EMIT16(c) do { \
    unsigned _b0h, _b1h, _b0l, _b1l; \
    PACK_H2(_b0h, vb, va); \
    PACK_H2(_b1h, vd, vc); \
    float _ra, _rb, _rc, _rd; \
    UNPACK_H2(_ra, _rb, _b0h); \
    UNPACK_H2(_rc, _rd, _b1h); \
    PACK_H2(_b0l, vb - _rb, va - _ra); \
    PACK_H2(_b1l, vd - _rd, vc - _rc); \
    MMA16(C[c], Ah, _b0h, _b1h); \
    MMA16(C[c], Ah, _b0l, _b1l); \
    MMA16(C[c], Al, _b0h, _b1h); \
} while (0)

// Faa di Bruno: accumulate w3 * jet(tanh(z)) into acc9[0..8]
__device__ __forceinline__ void compose_scalar(const float* z, float w3, float* acc9) {
    float f, f1, f2, f3;
    tanh_derivs(z[0], f, f1, f2, f3);
    const float zp = z[1], zt = z[2], zpp = z[3], zpt = z[4], ztt = z[5];
    const float zppp = z[6], zppt = z[7], zptt = z[8], zttt = z[9];
    acc9[0] = fmaf(w3, f1 * zp, acc9[0]);
    acc9[1] = fmaf(w3, f1 * zt, acc9[1]);
    acc9[2] = fmaf(w3, fmaf(f2, zp * zp, f1 * zpp), acc9[2]);
    acc9[3] = fmaf(w3, fmaf(f2, zp * zt, f1 * zpt), acc9[3]);
    acc9[4] = fmaf(w3, fmaf(f2, zt * zt, f1 * ztt), acc9[4]);
    acc9[5] = fmaf(w3, f3 * zp * zp * zp + 3.0f * f2 * zp * zpp + f1 * zppp, acc9[5]);
    acc9[6] = fmaf(w3, f3 * zp * zp * zt + f2 * (zpp * zt + 2.0f * zp * zpt) + f1 * zppt, acc9[6]);
    acc9[7] = fmaf(w3, f3 * zp * zt * zt + f2 * (ztt * zp + 2.0f * zt * zpt) + f1 * zptt, acc9[7]);
    acc9[8] = fmaf(w3, f3 * zt * zt * zt + 3.0f * f2 * zt * ztt + f1 * zttt, acc9[8]);
}

__global__ __launch_bounds__(THREADS, 5) void pinn_flow_kernel(
    const float* __restrict__ phi, const float* __restrict__ theta,
    const float* __restrict__ radius, const float* __restrict__ hth,
    const float* __restrict__ hph, const float* __restrict__ brr,
    const float* __restrict__ W1, const float* __restrict__ b1,
    const float* __restrict__ W2, const float* __restrict__ b2,
    const float* __restrict__ W3, const float* __restrict__ b3,
    float* __restrict__ out, int n)
{
    // fp16 A-fragment tables for W2^T (hi) and residual (lo), m16n8k16 layout:
    // [kq][chunk][lane]: a0 = (row g,   cols jA(lo), jB(hi))
    //                    a1 = (row g+8, cols jA, jB)
    //                    a2 = (row g,   cols jC, jD)
    //                    a3 = (row g+8, cols jC, jD)
    // g=lane>>2, t=lane&3, jA=chunk*16+2t, jB=jA+1, jC=jA+8, jD=jA+9, row base kq*16
    __shared__ __align__(16) uint4 sAh[4][4][32];   // 8 KB
    __shared__ __align__(16) uint4 sAl[4][4][32];   // 8 KB
    __shared__ __align__(16) float sL1[HH][12];     // a,b,aa,ab,bb,aaa,aab,abb,bbb,b1
    __shared__ float sB2[HH];
    __shared__ float sW3[HH];

    const int tid = threadIdx.x;

    for (int idx = tid; idx < 512; idx += THREADS) {
        const int kq    = idx >> 7;
        const int chunk = (idx >> 5) & 3;
        const int ln    = idx & 31;
        const int g = ln >> 2, t4 = ln & 3;
        const int kb = kq * 16;
        const int jA = chunk * 16 + 2 * t4;
        // W2^T[k][j] = W2[j*HH + k]
        float v[8], h[8], l[8];
        v[0] = W2[(jA    ) * HH + kb + g];      // (row g,   jA)
        v[1] = W2[(jA + 1) * HH + kb + g];      // (row g,   jB)
        v[2] = W2[(jA    ) * HH + kb + g + 8];  // (row g+8, jA)
        v[3] = W2[(jA + 1) * HH + kb + g + 8];  // (row g+8, jB)
        v[4] = W2[(jA + 8) * HH + kb + g];      // (row g,   jC)
        v[5] = W2[(jA + 9) * HH + kb + g];      // (row g,   jD)
        v[6] = W2[(jA + 8) * HH + kb + g + 8];  // (row g+8, jC)
        v[7] = W2[(jA + 9) * HH + kb + g + 8];  // (row g+8, jD)
        #pragma unroll
        for (int q = 0; q < 8; ++q) { h[q] = h2f_round(v[q]); l[q] = v[q] - h[q]; }
        uint4 Ah4, Al4;
        PACK_H2(Ah4.x, h[1], h[0]);
        PACK_H2(Ah4.y, h[3], h[2]);
        PACK_H2(Ah4.z, h[5], h[4]);
        PACK_H2(Ah4.w, h[7], h[6]);
        PACK_H2(Al4.x, l[1], l[0]);
        PACK_H2(Al4.y, l[3], l[2]);
        PACK_H2(Al4.z, l[5], l[4]);
        PACK_H2(Al4.w, l[7], l[6]);
        sAh[kq][chunk][ln] = Ah4;
        sAl[kq][chunk][ln] = Al4;
    }
    if (tid < HH) {
        sB2[tid] = b2[tid];
        sW3[tid] = W3[tid];
        const float a = W1[tid];        // W1[0][j]
        const float b = W1[HH + tid];   // W1[1][j]
        sL1[tid][0] = a;       sL1[tid][1] = b;
        sL1[tid][2] = a * a;   sL1[tid][3] = a * b;     sL1[tid][4] = b * b;
        sL1[tid][5] = a * a * a; sL1[tid][6] = a * a * b;
        sL1[tid][7] = a * b * b; sL1[tid][8] = b * b * b;
        sL1[tid][9] = b1[tid];
        sL1[tid][10] = 0.0f; sL1[tid][11] = 0.0f;
    }
    __syncthreads();

    const int lane = tid & 31;
    const int w    = tid >> 5;
    const int gid  = lane >> 2;   // 0..7  (point column)
    const int tig  = lane & 3;    // 0..3
    const int ntiles = (n + 31) >> 5;   // 32 points per block-tile (8 per warp)

    for (int tile = blockIdx.x; tile < ntiles; tile += gridDim.x) {
        const int base = tile * 32 + w * 8;     // this warp's 8 points
        const int myp  = base + gid;
        const int mypL = (myp < n) ? myp : (n - 1);
        const float p = phi[mypL];
        const float t = theta[mypL];

        float Tj[18];
        #pragma unroll
        for (int q = 0; q < 18; ++q) Tj[q] = 0.0f;

        #pragma unroll 1
        for (int kq = 0; kq < 4; ++kq) {
            float C[10][4];
            #pragma unroll
            for (int c = 0; c < 10; ++c) {
                C[c][0] = 0.0f; C[c][1] = 0.0f; C[c][2] = 0.0f; C[c][3] = 0.0f;
            }

            #pragma unroll 1
            for (int chunk = 0; chunk < 4; ++chunk) {
                const int jA = chunk * 16 + 2 * tig;   // B row 2t
                const int jB = jA + 1;                 // row 2t+1
                const int jC = jA + 8;                 // row 2t+8
                const int jD = jA + 9;                 // row 2t+9

                // monomials (a,b) and (bbb,b1) per j — kept live for c1,c2,c9
                const float2 eA = *(const float2*)&sL1[jA][0];
                const float2 eB = *(const float2*)&sL1[jB][0];
                const float2 eC = *(const float2*)&sL1[jC][0];
                const float2 eD = *(const float2*)&sL1[jD][0];
                const float2 gA = *(const float2*)&sL1[jA][8];
                const float2 gB = *(const float2*)&sL1[jB][8];
                const float2 gC = *(const float2*)&sL1[jC][8];
                const float2 gD = *(const float2*)&sL1[jD][8];

                float f0a, f1a, f2a, f3a, f0b, f1b, f2b, f3b;
                float f0c, f1c, f2c, f3c, f0d, f1d, f2d, f3d;
                tanh_derivs(fmaf(eA.x, p, fmaf(eA.y, t, gA.y)), f0a, f1a, f2a, f3a);
                tanh_derivs(fmaf(eB.x, p, fmaf(eB.y, t, gB.y)), f0b, f1b, f2b, f3b);
                tanh_derivs(fmaf(eC.x, p, fmaf(eC.y, t, gC.y)), f0c, f1c, f2c, f3c);
                tanh_derivs(fmaf(eD.x, p, fmaf(eD.y, t, gD.y)), f0d, f1d, f2d, f3d);

                const uint4 Ah = sAh[kq][chunk][lane];
                const uint4 Al = sAl[kq][chunk][lane];
                float va, vb, vc, vd;

                // c0: f
                va = f0a; vb = f0b; vc = f0c; vd = f0d;           EMIT16(0);
                // c1: f1*a ; c2: f1*b
                va = f1a * eA.x; vb = f1b * eB.x; vc = f1c * eC.x; vd = f1d * eD.x;  EMIT16(1);
                va = f1a * eA.y; vb = f1b * eB.y; vc = f1c * eC.y; vd = f1d * eD.y;  EMIT16(2);
                // c3: f2*aa ; c4: f2*ab   (monomials idx 2,3)
                {
                    const float2 qA = *(const float2*)&sL1[jA][2];
                    const float2 qB = *(const float2*)&sL1[jB][2];
                    const float2 qC = *(const float2*)&sL1[jC][2];
                    const float2 qD = *(const float2*)&sL1[jD][2];
                    va = f2a * qA.x; vb = f2b * qB.x; vc = f2c * qC.x; vd = f2d * qD.x;  EMIT16(3);
                    va = f2a * qA.y; vb = f2b * qB.y; vc = f2c * qC.y; vd = f2d * qD.y;  EMIT16(4);
                }
                // c5: f2*bb ; c6: f3*aaa  (idx 4,5)
                {
                    const float2 qA = *(const float2*)&sL1[jA][4];
                    const float2 qB = *(const float2*)&sL1[jB][4];
                    const float2 qC = *(const float2*)&sL1[jC][4];
                    const float2 qD = *(const float2*)&sL1[jD][4];
                    va = f2a * qA.x; vb = f2b * qB.x; vc = f2c * qC.x; vd = f2d * qD.x;  EMIT16(5);
                    va = f3a * qA.y; vb = f3b * qB.y; vc = f3c * qC.y; vd = f3d * qD.y;  EMIT16(6);
                }
                // c7: f3*aab ; c8: f3*abb (idx 6,7)
                {
                    const float2 qA = *(const float2*)&sL1[jA][6];
                    const float2 qB = *(const float2*)&sL1[jB][6];
                    const float2 qC = *(const float2*)&sL1[jC][6];
                    const float2 qD = *(const float2*)&sL1[jD][6];
                    va = f3a * qA.x; vb = f3b * qB.x; vc = f3c * qC.x; vd = f3d * qD.x;  EMIT16(7);
                    va = f3a * qA.y; vb = f3b * qB.y; vc = f3c * qC.y; vd = f3d * qD.y;  EMIT16(8);
                }
                // c9: f3*bbb (idx 8, already in gX.x)
                va = f3a * gA.x; vb = f3b * gB.x; vc = f3c * gC.x; vd = f3d * gD.x;      EMIT16(9);
            }

            // ---- compose this k-quarter's fragments into T-jet partials ----
            #pragma unroll
            for (int e = 0; e < 4; ++e) {
                const int k = kq * 16 + gid + ((e & 2) ? 8 : 0);
                float z[10];
                #pragma unroll
                for (int c = 0; c < 10; ++c) z[c] = C[c][e];
                z[0] += sB2[k];
                compose_scalar(z, sW3[k], &Tj[(e & 1) * 9]);
            }
        }

        // ---- reduce T-jet over the 8 lanes sharing each point-column ----
        #pragma unroll
        for (int q = 0; q < 18; ++q) {
            float v = Tj[q];
            v += __shfl_xor_sync(0xffffffffu, v, 4);
            v += __shfl_xor_sync(0xffffffffu, v, 8);
            v += __shfl_xor_sync(0xffffffffu, v, 16);
            Tj[q] = v;
        }

        // ---- epilogue: lanes 0..7 each finish one point ----
        if (lane < 8) {
            const int m   = lane & 3;
            const int sel = lane >> 2;
            const int pc  = 2 * m + sel;
            const int i   = base + pc;
            if (i < n) {
                const float* T = &Tj[sel * 9];
                const float Tp = T[0], Tt = T[1];
                const float Tpp = T[2], Tpt = T[3], Ttt = T[4];
                const float Tppp = T[5], Tppt = T[6], Tptt = T[7], Tttt = T[8];

                const float th = theta[i];
                float s, cn;
                sincosf(th, &s, &cn);
                const float r    = radius[i];
                const float invs = 1.0f / s;
                const float invr = 1.0f / r;

                const float ut = fmaf(Tp, invs, Tt);
                const float up = fmaf(Tp, invs, -Tt);

                const float u_th_t = -(Tpt + cn * Tt + s * Ttt);
                const float u_ph_p = fmaf(Tpp, invs, -Tpt);
                const float div = (u_th_t + u_ph_p) * invs * invr;

                const float c2s2 = cn * cn - s * s;
                const float u_th_tt = -(cn * Tpt + s * Tptt + 3.0f * s * cn * Ttt
                                        + c2s2 * Tt + s * s * Tttt);
                const float u_th_pp = -(fmaf(Tppp, invs, Tppt));
                const float u_ph_tt = cn * Tpt + s * Tptt - c2s2 * Tt
                                      - 3.0f * s * cn * Ttt - s * s * Tttt;
                const float u_ph_pp = fmaf(Tppp, invs, -Tppt);

                const float invr2  = invr * invr;
                const float invrs2 = invs * invs * invr2;
                const float lapt = fmaf(s * invr2, u_th_tt, u_th_pp * invrs2);
                const float lapp = fmaf(s * invr2, u_ph_tt, u_ph_pp * invrs2);
                const float comp = s * (lapt * lapt + lapp * lapp);
                const float sv   = -(ut * hth[i] + up * hph[i]) - brr[i] * div;
                const float tg   = div - ut * (s / cn) * invr;

                out[i]         = ut;
                out[n + i]     = up;
                out[2 * n + i] = div;
                out[3 * n + i] = sv;
                out[4 * n + i] = tg;
                out[5 * n + i] = comp;
            }
        }
    }
}

extern "C" void kernel_launch(void* const* d_in, const int* in_sizes, int n_in,
                              void* d_out, int out_size) {
    const float* phi    = (const float*)d_in[0];
    const float* theta  = (const float*)d_in[1];
    const float* radius = (const float*)d_in[2];
    const float* hth    = (const float*)d_in[3];
    const float* hph    = (const float*)d_in[4];
    const float* brr    = (const float*)d_in[5];
    const float* W1     = (const float*)d_in[6];
    const float* b1     = (const float*)d_in[7];
    const float* W2     = (const float*)d_in[8];
    const float* b2     = (const float*)d_in[9];
    const float* W3     = (const float*)d_in[10];
    const float* b3     = (const float*)d_in[11];
    float* out = (float*)d_out;
    const int n = in_sizes[0];

    pinn_flow_kernel<<<GRID_BLOCKS, THREADS>>>(
        phi, theta, radius, hth, hph, brr,
        W1, b1, W2, b2, W3, b3, out, n);
}

// round 12
// speedup vs baseline: 1.6130x; 1.1992x over previous
#include <cuda_runtime.h>
#include <cuda_bf16.h>
#include <cuda_fp16.h>

#define HH 64
#define GRID_BLOCKS 2048
#define THREADS 128

// fast tanh + first three derivatives via ex2.approx + rcp.approx
__device__ __forceinline__ void tanh_derivs(float x, float& f, float& f1, float& f2, float& f3) {
    float e, r;
    asm("ex2.approx.f32 %0, %1;" : "=f"(e) : "f"(x * 2.885390081777927f)); // 2*log2(e)
    asm("rcp.approx.f32 %0, %1;" : "=f"(r) : "f"(e + 1.0f));
    f  = fmaf(-2.0f, r, 1.0f);
    f1 = 1.0f - f * f;
    f2 = -2.0f * f * f1;
    f3 = -2.0f * (f1 * f1 + f * f2);
}

// pack two f32 into half2: first asm operand -> UPPER half
#define PACK_H2(d, hif, lof) \
    asm("cvt.rn.f16x2.f32 %0, %1, %2;" : "=r"(d) : "f"(hif), "f"(lof))

// f32 -> value exactly representable in f16 (round trip), for A-table build
__device__ __forceinline__ float h2f_round(float v) {
    float o;
    asm("{.reg .f16 t; cvt.rn.f16.f32 t, %1; cvt.f32.f16 %0, t;}" : "=f"(o) : "f"(v));
    return o;
}

// top-10-mantissa-bit truncation (f16-exact up to subnormal 2^-25 absolute slop)
__device__ __forceinline__ float mask_hi(float v) {
    return __uint_as_float(__float_as_uint(v) & 0xFFFFE000u);
}

// mma.m16n8k16 f16 inputs, f32 accumulate
#define MMA16(C, A, b0, b1) \
    asm("mma.sync.aligned.m16n8k16.row.col.f32.f16.f16.f32 " \
        "{%0,%1,%2,%3},{%4,%5,%6,%7},{%8,%9},{%0,%1,%2,%3};" \
        : "+f"((C)[0]), "+f"((C)[1]), "+f"((C)[2]), "+f"((C)[3]) \
        : "r"((A).x), "r"((A).y), "r"((A).z), "r"((A).w), "r"(b0), "r"(b1))

// split B (va..vd) once, feed TWO kq A-table pairs: 6 MMAs
#define EMIT16_2(c) do { \
    const float _ha = mask_hi(va), _hb = mask_hi(vb); \
    const float _hc = mask_hi(vc), _hd = mask_hi(vd); \
    unsigned _b0h, _b1h, _b0l, _b1l; \
    PACK_H2(_b0h, _hb, _ha); \
    PACK_H2(_b1h, _hd, _hc); \
    PACK_H2(_b0l, vb - _hb, va - _ha); \
    PACK_H2(_b1l, vd - _hd, vc - _hc); \
    MMA16(C0[c], Ah0, _b0h, _b1h); \
    MMA16(C0[c], Ah0, _b0l, _b1l); \
    MMA16(C0[c], Al0, _b0h, _b1h); \
    MMA16(C1[c], Ah1, _b0h, _b1h); \
    MMA16(C1[c], Ah1, _b0l, _b1l); \
    MMA16(C1[c], Al1, _b0h, _b1h); \
} while (0)

// Faa di Bruno: accumulate w3 * jet(tanh(z)) into acc9[0..8]
__device__ __forceinline__ void compose_scalar(const float* z, float w3, float* acc9) {
    float f, f1, f2, f3;
    tanh_derivs(z[0], f, f1, f2, f3);
    const float zp = z[1], zt = z[2], zpp = z[3], zpt = z[4], ztt = z[5];
    const float zppp = z[6], zppt = z[7], zptt = z[8], zttt = z[9];
    acc9[0] = fmaf(w3, f1 * zp, acc9[0]);
    acc9[1] = fmaf(w3, f1 * zt, acc9[1]);
    acc9[2] = fmaf(w3, fmaf(f2, zp * zp, f1 * zpp), acc9[2]);
    acc9[3] = fmaf(w3, fmaf(f2, zp * zt, f1 * zpt), acc9[3]);
    acc9[4] = fmaf(w3, fmaf(f2, zt * zt, f1 * ztt), acc9[4]);
    acc9[5] = fmaf(w3, f3 * zp * zp * zp + 3.0f * f2 * zp * zpp + f1 * zppp, acc9[5]);
    acc9[6] = fmaf(w3, f3 * zp * zp * zt + f2 * (zpp * zt + 2.0f * zp * zpt) + f1 * zppt, acc9[6]);
    acc9[7] = fmaf(w3, f3 * zp * zt * zt + f2 * (ztt * zp + 2.0f * zt * zpt) + f1 * zptt, acc9[7]);
    acc9[8] = fmaf(w3, f3 * zt * zt * zt + 3.0f * f2 * zt * ztt + f1 * zttt, acc9[8]);
}

__global__ __launch_bounds__(THREADS, 4) void pinn_flow_kernel(
    const float* __restrict__ phi, const float* __restrict__ theta,
    const float* __restrict__ radius, const float* __restrict__ hth,
    const float* __restrict__ hph, const float* __restrict__ brr,
    const float* __restrict__ W1, const float* __restrict__ b1,
    const float* __restrict__ W2, const float* __restrict__ b2,
    const float* __restrict__ W3, const float* __restrict__ b3,
    float* __restrict__ out, int n)
{
    // fp16 A-fragment tables for W2^T (hi) and residual (lo), m16n8k16 layout:
    // [kq][chunk][lane]: a0=(row g, jA|jB), a1=(row g+8, jA|jB), a2=(row g, jC|jD), a3=(row g+8, jC|jD)
    // g=lane>>2, t=lane&3, jA=chunk*16+2t, jB=jA+1, jC=jA+8, jD=jA+9, row base kq*16
    __shared__ __align__(16) uint4 sAh[4][4][32];   // 8 KB
    __shared__ __align__(16) uint4 sAl[4][4][32];   // 8 KB
    __shared__ __align__(16) float sL1[HH][12];     // a,b,aa,ab,bb,aaa,aab,abb,bbb,b1
    __shared__ float sB2[HH];
    __shared__ float sW3[HH];

    const int tid = threadIdx.x;

    for (int idx = tid; idx < 512; idx += THREADS) {
        const int kq    = idx >> 7;
        const int chunk = (idx >> 5) & 3;
        const int ln    = idx & 31;
        const int g = ln >> 2, t4 = ln & 3;
        const int kb = kq * 16;
        const int jA = chunk * 16 + 2 * t4;
        float v[8], h[8], l[8];
        v[0] = W2[(jA    ) * HH + kb + g];
        v[1] = W2[(jA + 1) * HH + kb + g];
        v[2] = W2[(jA    ) * HH + kb + g + 8];
        v[3] = W2[(jA + 1) * HH + kb + g + 8];
        v[4] = W2[(jA + 8) * HH + kb + g];
        v[5] = W2[(jA + 9) * HH + kb + g];
        v[6] = W2[(jA + 8) * HH + kb + g + 8];
        v[7] = W2[(jA + 9) * HH + kb + g + 8];
        #pragma unroll
        for (int q = 0; q < 8; ++q) { h[q] = h2f_round(v[q]); l[q] = v[q] - h[q]; }
        uint4 Ah4, Al4;
        PACK_H2(Ah4.x, h[1], h[0]);
        PACK_H2(Ah4.y, h[3], h[2]);
        PACK_H2(Ah4.z, h[5], h[4]);
        PACK_H2(Ah4.w, h[7], h[6]);
        PACK_H2(Al4.x, l[1], l[0]);
        PACK_H2(Al4.y, l[3], l[2]);
        PACK_H2(Al4.z, l[5], l[4]);
        PACK_H2(Al4.w, l[7], l[6]);
        sAh[kq][chunk][ln] = Ah4;
        sAl[kq][chunk][ln] = Al4;
    }
    if (tid < HH) {
        sB2[tid] = b2[tid];
        sW3[tid] = W3[tid];
        const float a = W1[tid];        // W1[0][j]
        const float b = W1[HH + tid];   // W1[1][j]
        sL1[tid][0] = a;       sL1[tid][1] = b;
        sL1[tid][2] = a * a;   sL1[tid][3] = a * b;     sL1[tid][4] = b * b;
        sL1[tid][5] = a * a * a; sL1[tid][6] = a * a * b;
        sL1[tid][7] = a * b * b; sL1[tid][8] = b * b * b;
        sL1[tid][9] = b1[tid];
        sL1[tid][10] = 0.0f; sL1[tid][11] = 0.0f;
    }
    __syncthreads();

    const int lane = tid & 31;
    const int w    = tid >> 5;
    const int gid  = lane >> 2;   // 0..7  (point column)
    const int tig  = lane & 3;    // 0..3
    const int ntiles = (n + 31) >> 5;   // 32 points per block-tile (8 per warp)

    for (int tile = blockIdx.x; tile < ntiles; tile += gridDim.x) {
        const int base = tile * 32 + w * 8;
        const int myp  = base + gid;
        const int mypL = (myp < n) ? myp : (n - 1);
        const float p = phi[mypL];
        const float t = theta[mypL];

        float Tj[18];
        #pragma unroll
        for (int q = 0; q < 18; ++q) Tj[q] = 0.0f;

        #pragma unroll 1
        for (int half = 0; half < 2; ++half) {
            const int kq0 = 2 * half;
            float C0[10][4], C1[10][4];
            #pragma unroll
            for (int c = 0; c < 10; ++c) {
                C0[c][0] = 0.0f; C0[c][1] = 0.0f; C0[c][2] = 0.0f; C0[c][3] = 0.0f;
                C1[c][0] = 0.0f; C1[c][1] = 0.0f; C1[c][2] = 0.0f; C1[c][3] = 0.0f;
            }

            #pragma unroll 1
            for (int chunk = 0; chunk < 4; ++chunk) {
                const int jA = chunk * 16 + 2 * tig;
                const int jB = jA + 1;
                const int jC = jA + 8;
                const int jD = jA + 9;

                const float2 eA = *(const float2*)&sL1[jA][0];
                const float2 eB = *(const float2*)&sL1[jB][0];
                const float2 eC = *(const float2*)&sL1[jC][0];
                const float2 eD = *(const float2*)&sL1[jD][0];
                const float2 gA = *(const float2*)&sL1[jA][8];
                const float2 gB = *(const float2*)&sL1[jB][8];
                const float2 gC = *(const float2*)&sL1[jC][8];
                const float2 gD = *(const float2*)&sL1[jD][8];

                float f0a, f1a, f2a, f3a, f0b, f1b, f2b, f3b;
                float f0c, f1c, f2c, f3c, f0d, f1d, f2d, f3d;
                tanh_derivs(fmaf(eA.x, p, fmaf(eA.y, t, gA.y)), f0a, f1a, f2a, f3a);
                tanh_derivs(fmaf(eB.x, p, fmaf(eB.y, t, gB.y)), f0b, f1b, f2b, f3b);
                tanh_derivs(fmaf(eC.x, p, fmaf(eC.y, t, gC.y)), f0c, f1c, f2c, f3c);
                tanh_derivs(fmaf(eD.x, p, fmaf(eD.y, t, gD.y)), f0d, f1d, f2d, f3d);

                const uint4 Ah0 = sAh[kq0][chunk][lane];
                const uint4 Al0 = sAl[kq0][chunk][lane];
                const uint4 Ah1 = sAh[kq0 + 1][chunk][lane];
                const uint4 Al1 = sAl[kq0 + 1][chunk][lane];
                float va, vb, vc, vd;

                // c0: f
                va = f0a; vb = f0b; vc = f0c; vd = f0d;                              EMIT16_2(0);
                // c1: f1*a ; c2: f1*b
                va = f1a * eA.x; vb = f1b * eB.x; vc = f1c * eC.x; vd = f1d * eD.x;  EMIT16_2(1);
                va = f1a * eA.y; vb = f1b * eB.y; vc = f1c * eC.y; vd = f1d * eD.y;  EMIT16_2(2);
                // c3: f2*aa ; c4: f2*ab
                {
                    const float2 qA = *(const float2*)&sL1[jA][2];
                    const float2 qB = *(const float2*)&sL1[jB][2];
                    const float2 qC = *(const float2*)&sL1[jC][2];
                    const float2 qD = *(const float2*)&sL1[jD][2];
                    va = f2a * qA.x; vb = f2b * qB.x; vc = f2c * qC.x; vd = f2d * qD.x;  EMIT16_2(3);
                    va = f2a * qA.y; vb = f2b * qB.y; vc = f2c * qC.y; vd = f2d * qD.y;  EMIT16_2(4);
                }
                // c5: f2*bb ; c6: f3*aaa
                {
                    const float2 qA = *(const float2*)&sL1[jA][4];
                    const float2 qB = *(const float2*)&sL1[jB][4];
                    const float2 qC = *(const float2*)&sL1[jC][4];
                    const float2 qD = *(const float2*)&sL1[jD][4];
                    va = f2a * qA.x; vb = f2b * qB.x; vc = f2c * qC.x; vd = f2d * qD.x;  EMIT16_2(5);
                    va = f3a * qA.y; vb = f3b * qB.y; vc = f3c * qC.y; vd = f3d * qD.y;  EMIT16_2(6);
                }
                // c7: f3*aab ; c8: f3*abb
                {
                    const float2 qA = *(const float2*)&sL1[jA][6];
                    const float2 qB = *(const float2*)&sL1[jB][6];
                    const float2 qC = *(const float2*)&sL1[jC][6];
                    const float2 qD = *(const float2*)&sL1[jD][6];
                    va = f3a * qA.x; vb = f3b * qB.x; vc = f3c * qC.x; vd = f3d * qD.x;  EMIT16_2(7);
                    va = f3a * qA.y; vb = f3b * qB.y; vc = f3c * qC.y; vd = f3d * qD.y;  EMIT16_2(8);
                }
                // c9: f3*bbb
                va = f3a * gA.x; vb = f3b * gB.x; vc = f3c * gC.x; vd = f3d * gD.x;      EMIT16_2(9);
            }

            // ---- compose both kq of this half into T-jet partials ----
            #pragma unroll
            for (int e = 0; e < 4; ++e) {
                const int krow = gid + ((e & 2) ? 8 : 0);
                float z[10];
                #pragma unroll
                for (int c = 0; c < 10; ++c) z[c] = C0[c][e];
                z[0] += sB2[kq0 * 16 + krow];
                compose_scalar(z, sW3[kq0 * 16 + krow], &Tj[(e & 1) * 9]);
                #pragma unroll
                for (int c = 0; c < 10; ++c) z[c] = C1[c][e];
                z[0] += sB2[(kq0 + 1) * 16 + krow];
                compose_scalar(z, sW3[(kq0 + 1) * 16 + krow], &Tj[(e & 1) * 9]);
            }
        }

        // ---- reduce T-jet over the 8 lanes sharing each point-column ----
        #pragma unroll
        for (int q = 0; q < 18; ++q) {
            float v = Tj[q];
            v += __shfl_xor_sync(0xffffffffu, v, 4);
            v += __shfl_xor_sync(0xffffffffu, v, 8);
            v += __shfl_xor_sync(0xffffffffu, v, 16);
            Tj[q] = v;
        }

        // ---- epilogue: lanes 0..7 each finish one point ----
        if (lane < 8) {
            const int m   = lane & 3;
            const int sel = lane >> 2;
            const int pc  = 2 * m + sel;
            const int i   = base + pc;
            if (i < n) {
                const float* T = &Tj[sel * 9];
                const float Tp = T[0], Tt = T[1];
                const float Tpp = T[2], Tpt = T[3], Ttt = T[4];
                const float Tppp = T[5], Tppt = T[6], Tptt = T[7], Tttt = T[8];

                const float th = theta[i];
                float s, cn;
                sincosf(th, &s, &cn);
                const float r    = radius[i];
                const float invs = 1.0f / s;
                const float invr = 1.0f / r;

                const float ut = fmaf(Tp, invs, Tt);
                const float up = fmaf(Tp, invs, -Tt);

                const float u_th_t = -(Tpt + cn * Tt + s * Ttt);
                const float u_ph_p = fmaf(Tpp, invs, -Tpt);
                const float div = (u_th_t + u_ph_p) * invs * invr;

                const float c2s2 = cn * cn - s * s;
                const float u_th_tt = -(cn * Tpt + s * Tptt + 3.0f * s * cn * Ttt
                                        + c2s2 * Tt + s * s * Tttt);
                const float u_th_pp = -(fmaf(Tppp, invs, Tppt));
                const float u_ph_tt = cn * Tpt + s * Tptt - c2s2 * Tt
                                      - 3.0f * s * cn * Ttt - s * s * Tttt;
                const float u_ph_pp = fmaf(Tppp, invs, -Tppt);

                const float invr2  = invr * invr;
                const float invrs2 = invs * invs * invr2;
                const float lapt = fmaf(s * invr2, u_th_tt, u_th_pp * invrs2);
                const float lapp = fmaf(s * invr2, u_ph_tt, u_ph_pp * invrs2);
                const float comp = s * (lapt * lapt + lapp * lapp);
                const float sv   = -(ut * hth[i] + up * hph[i]) - brr[i] * div;
                const float tg   = div - ut * (s / cn) * invr;

                out[i]         = ut;
                out[n + i]     = up;
                out[2 * n + i] = div;
                out[3 * n + i] = sv;
                out[4 * n + i] = tg;
                out[5 * n + i] = comp;
            }
        }
    }
}

extern "C" void kernel_launch(void* const* d_in, const int* in_sizes, int n_in,
                              void* d_out, int out_size) {
    const float* phi    = (const float*)d_in[0];
    const float* theta  = (const float*)d_in[1];
    const float* radius = (const float*)d_in[2];
    const float* hth    = (const float*)d_in[3];
    const float* hph    = (const float*)d_in[4];
    const float* brr    = (const float*)d_in[5];
    const float* W1     = (const float*)d_in[6];
    const float* b1     = (const float*)d_in[7];
    const float* W2     = (const float*)d_in[8];
    const float* b2     = (const float*)d_in[9];
    const float* W3     = (const float*)d_in[10];
    const float* b3     = (const float*)d_in[11];
    float* out = (float*)d_out;
    const int n = in_sizes[0];

    pinn_flow_kernel<<<GRID_BLOCKS, THREADS>>>(
        phi, theta, radius, hth, hph, brr,
        W1, b1, W2, b2, W3, b3, out, n);
}